// round 6
// baseline (speedup 1.0000x reference)
#include <cuda_runtime.h>
#include <cstdint>

#define B_  256
#define T_  2048
#define K2_ 52

// scratch (device globals: no allocations allowed)
__device__ float g_fw[B_];
__device__ float g_diff[B_];
__device__ int   g_len[B_];
__device__ int   g_ord[B_];
__device__ int   g_i64;    // 1 if lengths/labels buffers are int64, 0 if int32

#define FFMA2(d,a,b,c) asm("fma.rn.f32x2 %0, %1, %2, %3;" : "=l"(d) : "l"(a), "l"(b), "l"(c))
#define FADD2(d,a,b)   asm("add.rn.f32x2 %0, %1, %2;"     : "=l"(d) : "l"(a), "l"(b))

// ---------------------------------------------------------------------------
// Prep: detect int32 vs int64 for lengths (values in [1,2048], never 0).
// ---------------------------------------------------------------------------
__global__ void prep_kernel(const void* __restrict__ lens_raw)
{
    __shared__ int orred;
    __shared__ int slen[B_];
    const int tid = threadIdx.x;   // 0..255
    if (tid == 0) orred = 0;
    __syncthreads();
    const int* w = (const int*)lens_raw;
    const int v = w[tid];
    if (tid & 1) atomicOr(&orred, v);
    __syncthreads();
    const int is64 = (orred == 0) ? 1 : 0;
    const int len = is64 ? (int)(((const long long*)lens_raw)[tid]) : v;
    g_len[tid] = len;
    slen[tid] = len;
    if (tid == 0) g_i64 = is64;
    __syncthreads();
    int rank = 0;
    for (int j = 0; j < B_; ++j) {
        int lj = slen[j];
        if (lj > len || (lj == len && j < tid)) ++rank;
    }
    g_ord[rank] = tid;
}

// ---------------------------------------------------------------------------
// Forward: 128 threads/block, one batch/block. Lane pair (2s, 2s+1) owns
// state s; half h covers prev states [28h, 28h+28). Each half stores its
// SCALED partial to its own buffer (vbA for h=0, vbB for h=1); the next
// step pre-adds the two buffers pairwise (exact by linearity). Renorm
// reference = vbA[0]+vbB[0] (total v[0]) with zero-guard, every 2nd step,
// exact power-of-two factor. x8-unrolled loop, static emission ring.
// ---------------------------------------------------------------------------
__global__ __launch_bounds__(128)
void fwd_kernel(const float* __restrict__ em,
                const float* __restrict__ tr)
{
    const int b   = g_ord[blockIdx.x];
    const int tid = threadIdx.x;                // 0..127
    const int s   = tid >> 1;                   // state 0..63
    const int h   = tid & 1;                    // half 0/1
    const int srow = (s < K2_) ? s : (K2_ - 1); // clamp for idle lanes
    const bool act = (s < K2_);
    const int len = g_len[b];
    const int hbase = h * 28;

    __shared__ __align__(16) float vbA[2][56];  // h=0 partials (scaled)
    __shared__ __align__(16) float vbB[2][56];  // h=1 partials (scaled)
    __shared__ float red[64];

    // Packed half M row: m2[j] = (expT[p0], expT[p1]), p = hbase + 2j(+1);
    // coefficients for prev >= 52 are 0 (pads).
    unsigned long long m2[14];
    {
        const float* row = tr + srow * K2_;
#pragma unroll
        for (int j = 0; j < 14; ++j) {
            int p0 = hbase + 2 * j, p1 = p0 + 1;
            float a = (p0 < K2_) ? __expf(row[p0]) : 0.0f;
            float c = (p1 < K2_) ? __expf(row[p1]) : 0.0f;
            asm("mov.b64 %0, {%1, %2};" : "=l"(m2[j]) : "f"(a), "f"(c));
        }
    }

    // init: A = one-hot(START=50), B = 0, pads 0, both ping-pong slots
    if (tid < 56) {
        vbA[0][tid] = (tid == 50) ? 1.0f : 0.0f;
        vbA[1][tid] = 0.0f;
        vbB[0][tid] = 0.0f;
        vbB[1][tid] = 0.0f;
    }

    // output buffer for this lane's half
    float* outbuf = h ? &vbB[0][0] : &vbA[0][0];   // [DST*56 + s]

    // emission prefetch ring (distance 8, static slots)
    const float* eb = em + ((size_t)b * T_) * K2_ + srow;
    float eraw[8];
#pragma unroll
    for (int i = 0; i < 8; ++i) {
        int idx = (i < len) ? i : (len - 1);
        eraw[i] = eb[(size_t)idx * K2_];
    }

    int lz = 0;      // sum of power-of-two exponents (exact)
    __syncthreads();

#define STEP(EI, SRC, DST, DOREN, TCUR) do {                                  \
    const float E_ = __expf(eraw[EI]);                                        \
    float scale_;                                                             \
    if (DOREN) {                                                              \
        float t0_ = vbA[SRC][0] + vbB[SRC][0];                                \
        unsigned bits_ = __float_as_uint(t0_);                                \
        int e_ = 0;                                                           \
        if (bits_) {                                                          \
            e_ = (int)((bits_ >> 23) & 0xff) - 127;                           \
            e_ = max(-126, min(126, e_));                                     \
        }                                                                     \
        lz += e_;                                                             \
        scale_ = __uint_as_float((unsigned)(127 - e_) << 23) * E_;            \
    } else {                                                                  \
        scale_ = E_;                                                          \
    }                                                                         \
    const ulonglong2* VA_ = reinterpret_cast<const ulonglong2*>(vbA[SRC] + hbase); \
    const ulonglong2* VB_ = reinterpret_cast<const ulonglong2*>(vbB[SRC] + hbase); \
    unsigned long long a0_=0ULL, a1_=0ULL, a2_=0ULL, a3_=0ULL;                \
    _Pragma("unroll")                                                         \
    for (int j_ = 0; j_ < 7; ++j_) {                                          \
        ulonglong2 va_ = VA_[j_];                                             \
        ulonglong2 vb_ = VB_[j_];                                             \
        unsigned long long s0_, s1_;                                          \
        FADD2(s0_, va_.x, vb_.x);                                             \
        FADD2(s1_, va_.y, vb_.y);                                             \
        if (j_ & 1) { FFMA2(a2_, m2[2*j_],   s0_, a2_);                       \
                      FFMA2(a3_, m2[2*j_+1], s1_, a3_); }                     \
        else        { FFMA2(a0_, m2[2*j_],   s0_, a0_);                       \
                      FFMA2(a1_, m2[2*j_+1], s1_, a1_); }                     \
    }                                                                         \
    FADD2(a0_, a0_, a2_);                                                     \
    FADD2(a1_, a1_, a3_);                                                     \
    FADD2(a0_, a0_, a1_);                                                     \
    float qlo_ = __uint_as_float((unsigned)(a0_ & 0xffffffffULL));            \
    float qhi_ = __uint_as_float((unsigned)(a0_ >> 32));                      \
    if (act) outbuf[(DST) * 56 + s] = (qlo_ + qhi_) * scale_;                 \
    { int idx_ = (TCUR) + 8; idx_ = (idx_ > len - 1) ? (len - 1) : idx_;      \
      eraw[EI] = eb[(size_t)idx_ * K2_]; }                                    \
    __syncthreads();                                                          \
} while (0)

    int t = 0;
    const int nmain = len & ~7;
    for (; t < nmain; t += 8) {
        STEP(0, 0, 1, true,  t + 0);
        STEP(1, 1, 0, false, t + 1);
        STEP(2, 0, 1, true,  t + 2);
        STEP(3, 1, 0, false, t + 3);
        STEP(4, 0, 1, true,  t + 4);
        STEP(5, 1, 0, false, t + 5);
        STEP(6, 0, 1, true,  t + 6);
        STEP(7, 1, 0, false, t + 7);
    }
    // tail (0..7 steps), static ring slots since nmain % 8 == 0
    if (t < len) { STEP(0, 0, 1, true, t); ++t; }
    if (t < len) { STEP(1, 1, 0, true, t); ++t; }
    if (t < len) { STEP(2, 0, 1, true, t); ++t; }
    if (t < len) { STEP(3, 1, 0, true, t); ++t; }
    if (t < len) { STEP(4, 0, 1, true, t); ++t; }
    if (t < len) { STEP(5, 1, 0, true, t); ++t; }
    if (t < len) { STEP(6, 0, 1, true, t); ++t; }
#undef STEP

    // final state lives in slot (len & 1); v[s] = A[s] + B[s]
    const int fin = len & 1;

    // terminal: fw = lz*ln2 + log( sum_s exp(trans[STOP][s]) * v[s] )
    if (h == 0 && act) {
        float vfs = vbA[fin][s] + vbB[fin][s];
        red[s] = __expf(tr[(K2_ - 1) * K2_ + s]) * vfs;
    }
    __syncthreads();
    if (tid == 0) {
        float acc = 0.0f;
        for (int i = 0; i < K2_; ++i) acc += red[i];
        g_fw[b] = (float)((double)lz * 0.69314718055994530942) + __logf(acc);
    }
}

// ---------------------------------------------------------------------------
// Gold score: one batch per 256-thread block.
// ---------------------------------------------------------------------------
__global__ void gold_kernel(const float* __restrict__ em,
                            const float* __restrict__ tr,
                            const void* __restrict__ labs_raw)
{
    const int b = blockIdx.x;
    const int tid = threadIdx.x;
    const int len = g_len[b];
    const int is64 = g_i64;
    const long long* lb64 = ((const long long*)labs_raw) + (size_t)b * T_;
    const int*       lb32 = ((const int*)labs_raw) + (size_t)b * T_;

    float acc = 0.0f;
    for (int t = tid; t < len; t += 256) {
        int lab  = is64 ? (int)lb64[t] : lb32[t];
        acc += em[((size_t)b * T_ + t) * K2_ + lab];
        int prev = (t == 0) ? (K2_ - 2)
                            : (is64 ? (int)lb64[t - 1] : lb32[t - 1]);
        acc += tr[lab * K2_ + prev];
    }

    __shared__ float sm[256];
    sm[tid] = acc;
    __syncthreads();
    for (int off = 128; off > 0; off >>= 1) {
        if (tid < off) sm[tid] += sm[tid + off];
        __syncthreads();
    }
    if (tid == 0) {
        int lastlab = is64 ? (int)lb64[len - 1] : lb32[len - 1];
        float gold = sm[0] + tr[(K2_ - 1) * K2_ + lastlab];
        g_diff[b] = g_fw[b] - gold;
    }
}

// ---------------------------------------------------------------------------
// Deterministic final mean over 256 batches.
// ---------------------------------------------------------------------------
__global__ void reduce_kernel(float* __restrict__ out)
{
    const int tid = threadIdx.x;
    __shared__ float sm[256];
    sm[tid] = g_diff[tid];
    __syncthreads();
    for (int off = 128; off > 0; off >>= 1) {
        if (tid < off) sm[tid] += sm[tid + off];
        __syncthreads();
    }
    if (tid == 0) out[0] = sm[0] * (1.0f / 256.0f);
}

extern "C" void kernel_launch(void* const* d_in, const int* in_sizes, int n_in,
                              void* d_out, int out_size)
{
    const float* em   = (const float*)d_in[0];   // [B, T, K2] f32
    const float* tr   = (const float*)d_in[1];   // [K2, K2]   f32
    const void*  lens = d_in[2];                 // [B]    i32 or i64
    const void*  labs = d_in[3];                 // [B, T] i32 or i64

    prep_kernel<<<1, 256>>>(lens);
    fwd_kernel<<<B_, 128>>>(em, tr);
    gold_kernel<<<B_, 256>>>(em, tr, labs);
    reduce_kernel<<<1, 256>>>((float*)d_out);
}